// round 2
// baseline (speedup 1.0000x reference)
#include <cuda_runtime.h>
#include <cuda_bf16.h>

#define EPS 1e-6f

// ---------------- device scratch (no allocations allowed) ----------------
__device__ float4 g_params[4096];      // per (b,t): {1+scale, shift, sigmoid(gate), 0}
__device__ int    g_valid[16 * 4096];  // per batch: compacted flat indices (t*16+c)
__device__ int    g_count[16];         // per batch: number of valid chars

// ---------------- packed f32x2 helpers (B300 FFMA2 path) ----------------
__device__ __forceinline__ unsigned long long pack2(float x, float y) {
    unsigned long long r;
    asm("mov.b64 %0, {%1, %2};" : "=l"(r) : "f"(x), "f"(y));
    return r;
}
__device__ __forceinline__ void unpack2(unsigned long long v, float& x, float& y) {
    asm("mov.b64 {%0, %1}, %2;" : "=f"(x), "=f"(y) : "l"(v));
}
__device__ __forceinline__ void ffma2(unsigned long long& d, unsigned long long a,
                                      unsigned long long b) {
    asm("fma.rn.f32x2 %0, %1, %2, %0;" : "+l"(d) : "l"(a), "l"(b));
}
__device__ __forceinline__ float silu_f(float z) { return z / (1.0f + __expf(-z)); }

// ---------------- kernel 0: per-batch mask scan / compaction ----------------
// char_ids_mask is a bool array promoted to int32 by the harness.
__global__ void k_scan(const int* __restrict__ mask) {
    int b = blockIdx.x, tid = threadIdx.x;
    __shared__ int s[256];
    const int* m = mask + b * 4096 + tid * 16;
    unsigned flags = 0;
    int cnt = 0;
#pragma unroll
    for (int i = 0; i < 16; i++)
        if (m[i] != 0) { flags |= (1u << i); cnt++; }
    s[tid] = cnt;
    __syncthreads();
    for (int off = 1; off < 256; off <<= 1) {
        int v = (tid >= off) ? s[tid - off] : 0;
        __syncthreads();
        s[tid] += v;
        __syncthreads();
    }
    int base = s[tid] - cnt;
    int ib = b * 4096;
#pragma unroll
    for (int i = 0; i < 16; i++)
        if (flags & (1u << i)) g_valid[ib + base++] = tid * 16 + i;
    if (tid == 255) g_count[b] = s[255];
}

// ---------------- kernel 1: per-token params ----------------
// block = 16 tokens, 256 threads. rmsnorm -> GEMM1(1024->512, FFMA2) ->
// rmsnorm -> silu -> W_proj(3) -> store (1+scale, shift, sigmoid(gate)).
__global__ __launch_bounds__(256) void k_params(
    const float* __restrict__ tok, const float* __restrict__ w_pre,
    const float* __restrict__ w_tok, const float* __restrict__ Wd,
    const float* __restrict__ Wp) {
    extern __shared__ float sm[];
    float* xs = sm;          // transposed normalized tokens: xs[k*20 + r], k<1024
    float* Ws = sm + 20480;  // staged W_down chunk: Ws[kk*520 + e], kk<16
    int tid = threadIdx.x;
    int tok0 = blockIdx.x * 16;
    int r = tid >> 4, q = tid & 15;

    // --- rmsnorm #1 (16 threads per row, 64 elems each) ---
    const float4* xrow = (const float4*)(tok + (size_t)(tok0 + r) * 1024);
    float ss = 0.f;
#pragma unroll
    for (int i = 0; i < 16; i++) {
        float4 v = xrow[q + 16 * i];
        ss += v.x * v.x + v.y * v.y + v.z * v.z + v.w * v.w;
    }
#pragma unroll
    for (int o = 8; o >= 1; o >>= 1) ss += __shfl_xor_sync(0xffffffffu, ss, o);
    float inv = rsqrtf(ss * (1.0f / 1024.0f) + EPS);
    const float4* wpre4 = (const float4*)w_pre;
#pragma unroll
    for (int i = 0; i < 16; i++) {
        int f4 = q + 16 * i;
        float4 v = xrow[f4];
        float4 w = wpre4[f4];
        int k = f4 * 4;
        xs[(k + 0) * 20 + r] = v.x * inv * w.x;
        xs[(k + 1) * 20 + r] = v.y * inv * w.y;
        xs[(k + 2) * 20 + r] = v.z * inv * w.z;
        xs[(k + 3) * 20 + r] = v.w * inv * w.w;
    }

    // --- GEMM1: feats[16][512] = xn @ W_down^T, thread owns cols (tid, tid+256) ---
    int c0 = tid, c1 = tid + 256;
    unsigned long long a0[8], a1[8];
#pragma unroll
    for (int i = 0; i < 8; i++) { a0[i] = 0ull; a1[i] = 0ull; }
    const float4* Wd4 = (const float4*)Wd;
    for (int k0 = 0; k0 < 1024; k0 += 16) {
        __syncthreads();
        for (int f = tid; f < 2048; f += 256) {
            int e = f >> 2, kq = (f & 3) << 2;
            float4 w = Wd4[e * 256 + ((k0 + kq) >> 2)];
            Ws[(kq + 0) * 520 + e] = w.x;
            Ws[(kq + 1) * 520 + e] = w.y;
            Ws[(kq + 2) * 520 + e] = w.z;
            Ws[(kq + 3) * 520 + e] = w.w;
        }
        __syncthreads();
#pragma unroll
        for (int kk = 0; kk < 16; kk++) {
            const float* xk = xs + (k0 + kk) * 20;
            ulonglong2 xa = *(const ulonglong2*)(xk);
            ulonglong2 xb = *(const ulonglong2*)(xk + 4);
            ulonglong2 xc = *(const ulonglong2*)(xk + 8);
            ulonglong2 xd = *(const ulonglong2*)(xk + 12);
            float w0 = Ws[kk * 520 + c0];
            float w1 = Ws[kk * 520 + c1];
            unsigned long long w0d = pack2(w0, w0);
            unsigned long long w1d = pack2(w1, w1);
            ffma2(a0[0], xa.x, w0d); ffma2(a0[1], xa.y, w0d);
            ffma2(a0[2], xb.x, w0d); ffma2(a0[3], xb.y, w0d);
            ffma2(a0[4], xc.x, w0d); ffma2(a0[5], xc.y, w0d);
            ffma2(a0[6], xd.x, w0d); ffma2(a0[7], xd.y, w0d);
            ffma2(a1[0], xa.x, w1d); ffma2(a1[1], xa.y, w1d);
            ffma2(a1[2], xb.x, w1d); ffma2(a1[3], xb.y, w1d);
            ffma2(a1[4], xc.x, w1d); ffma2(a1[5], xc.y, w1d);
            ffma2(a1[6], xd.x, w1d); ffma2(a1[7], xd.y, w1d);
        }
    }
    __syncthreads();

    // --- spill feats to smem (reuse xs region) ---
    float* fs = sm;  // [16][512]
#pragma unroll
    for (int rp = 0; rp < 8; rp++) {
        float y0, y1;
        unpack2(a0[rp], y0, y1);
        fs[(2 * rp) * 512 + c0] = y0;
        fs[(2 * rp + 1) * 512 + c0] = y1;
        unpack2(a1[rp], y0, y1);
        fs[(2 * rp) * 512 + c1] = y0;
        fs[(2 * rp + 1) * 512 + c1] = y1;
    }
    __syncthreads();

    // --- rmsnorm #2 + silu + W_proj: warp w handles rows w and w+8 ---
    int warp = tid >> 5, lane = tid & 31;
    for (int rr = 0; rr < 2; rr++) {
        int rw = warp + rr * 8;
        const float* fr = fs + rw * 512;
        float s2 = 0.f;
#pragma unroll
        for (int i = 0; i < 16; i++) {
            float v = fr[lane + 32 * i];
            s2 += v * v;
        }
#pragma unroll
        for (int o = 16; o >= 1; o >>= 1) s2 += __shfl_xor_sync(0xffffffffu, s2, o);
        float inv2 = rsqrtf(s2 * (1.0f / 512.0f) + EPS);
        float p0 = 0.f, p1 = 0.f, p2 = 0.f;
#pragma unroll
        for (int i = 0; i < 16; i++) {
            int d = lane + 32 * i;
            float v = fr[d] * inv2 * w_tok[d];
            float sv = silu_f(v);
            p0 += sv * Wp[d];
            p1 += sv * Wp[512 + d];
            p2 += sv * Wp[1024 + d];
        }
#pragma unroll
        for (int o = 16; o >= 1; o >>= 1) {
            p0 += __shfl_xor_sync(0xffffffffu, p0, o);
            p1 += __shfl_xor_sync(0xffffffffu, p1, o);
            p2 += __shfl_xor_sync(0xffffffffu, p2, o);
        }
        if (lane == 0) {
            float4 pr;
            pr.x = 1.0f + p0;
            pr.y = p1;
            pr.z = 1.0f / (1.0f + __expf(-p2));
            pr.w = 0.f;
            g_params[tok0 + rw] = pr;
        }
    }
}

// ---------------- kernel 2: fused char rmsnorm + modulated silu + GEMM2 + gate mix + scatter ---
// block = 16 compacted output rows of one batch; 256 threads, cols (tid, tid+256).
__global__ __launch_bounds__(256) void k_fusion(
    const float* __restrict__ ch, const float* __restrict__ w_char,
    const float* __restrict__ Wf, const float* __restrict__ filler,
    float* __restrict__ out) {
    extern __shared__ float sm[];
    float* cn = sm;                         // [16][512]
    float* us = sm + 8192;                  // transposed u: us[k*20 + r], k<512
    float* Ws = sm + 8192 + 10240;          // [16][520] staged W_fusion chunk
    float* g_sh = sm + 8192 + 10240 + 8320; // [16] gates
    int* v_sh = (int*)(g_sh + 16);          // [16] valid flags

    int tid = threadIdx.x;
    int b = blockIdx.x >> 8;
    int j0 = (blockIdx.x & 255) << 4;
    int cnt = g_count[b];
    int c0 = tid, c1 = tid + 256;

    if (j0 >= cnt) {  // entire tile is filler: broadcast and exit
        float f0 = filler[c0], f1 = filler[c1];
        float* ob = out + (size_t)(b * 4096 + j0) * 512;
#pragma unroll
        for (int r = 0; r < 16; r++) {
            ob[r * 512 + c0] = f0;
            ob[r * 512 + c1] = f1;
        }
        return;
    }

    int r = tid >> 4, q = tid & 15;
    int j = j0 + r;
    bool valid = j < cnt;
    float s1 = 0.f, shf = 0.f, gg = 0.f;
    const float4* xrow = (const float4*)ch;  // dummy init
    if (valid) {
        int flat = g_valid[b * 4096 + j];
        int t = flat >> 4;
        xrow = (const float4*)(ch + (size_t)((b * 256 + t) * 16 + (flat & 15)) * 512);
        float4 p = g_params[b * 256 + t];
        s1 = p.x;
        shf = p.y;
        gg = p.z;
    }
    if (q == 0) {
        g_sh[r] = gg;
        v_sh[r] = valid ? 1 : 0;
    }

    // --- char rmsnorm + modulated silu ---
    float4 xv[8];
    float ssq = 0.f;
    if (valid) {
#pragma unroll
        for (int i = 0; i < 8; i++) {
            float4 v = xrow[q + 16 * i];
            xv[i] = v;
            ssq += v.x * v.x + v.y * v.y + v.z * v.z + v.w * v.w;
        }
    }
#pragma unroll
    for (int o = 8; o >= 1; o >>= 1) ssq += __shfl_xor_sync(0xffffffffu, ssq, o);
    float inv = rsqrtf(ssq * (1.0f / 512.0f) + EPS);
    const float4* wch4 = (const float4*)w_char;
    if (valid) {
#pragma unroll
        for (int i = 0; i < 8; i++) {
            int f4 = q + 16 * i;
            float4 w = wch4[f4];
            float4 v = xv[i];
            float4 cv;
            cv.x = v.x * inv * w.x;
            cv.y = v.y * inv * w.y;
            cv.z = v.z * inv * w.z;
            cv.w = v.w * inv * w.w;
            *(float4*)(cn + r * 512 + f4 * 4) = cv;
            int k = f4 * 4;
            us[(k + 0) * 20 + r] = silu_f(cv.x * s1 + shf);
            us[(k + 1) * 20 + r] = silu_f(cv.y * s1 + shf);
            us[(k + 2) * 20 + r] = silu_f(cv.z * s1 + shf);
            us[(k + 3) * 20 + r] = silu_f(cv.w * s1 + shf);
        }
    } else {
#pragma unroll
        for (int i = 0; i < 8; i++) {
            int k = (q + 16 * i) * 4;
            us[(k + 0) * 20 + r] = 0.f;
            us[(k + 1) * 20 + r] = 0.f;
            us[(k + 2) * 20 + r] = 0.f;
            us[(k + 3) * 20 + r] = 0.f;
        }
    }

    // --- GEMM2: y[16][512] = u @ W_fusion^T (packed f32x2 FFMA) ---
    unsigned long long a0[8], a1[8];
#pragma unroll
    for (int i = 0; i < 8; i++) { a0[i] = 0ull; a1[i] = 0ull; }
    const float4* Wf4 = (const float4*)Wf;
    for (int k0 = 0; k0 < 512; k0 += 16) {
        __syncthreads();
        for (int f = tid; f < 2048; f += 256) {
            int e = f >> 2, kq = (f & 3) << 2;
            float4 w = Wf4[e * 128 + ((k0 + kq) >> 2)];
            Ws[(kq + 0) * 520 + e] = w.x;
            Ws[(kq + 1) * 520 + e] = w.y;
            Ws[(kq + 2) * 520 + e] = w.z;
            Ws[(kq + 3) * 520 + e] = w.w;
        }
        __syncthreads();
#pragma unroll
        for (int kk = 0; kk < 16; kk++) {
            const float* xk = us + (k0 + kk) * 20;
            ulonglong2 xa = *(const ulonglong2*)(xk);
            ulonglong2 xb = *(const ulonglong2*)(xk + 4);
            ulonglong2 xc = *(const ulonglong2*)(xk + 8);
            ulonglong2 xd = *(const ulonglong2*)(xk + 12);
            float w0 = Ws[kk * 520 + c0];
            float w1 = Ws[kk * 520 + c1];
            unsigned long long w0d = pack2(w0, w0);
            unsigned long long w1d = pack2(w1, w1);
            ffma2(a0[0], xa.x, w0d); ffma2(a0[1], xa.y, w0d);
            ffma2(a0[2], xb.x, w0d); ffma2(a0[3], xb.y, w0d);
            ffma2(a0[4], xc.x, w0d); ffma2(a0[5], xc.y, w0d);
            ffma2(a0[6], xd.x, w0d); ffma2(a0[7], xd.y, w0d);
            ffma2(a1[0], xa.x, w1d); ffma2(a1[1], xa.y, w1d);
            ffma2(a1[2], xb.x, w1d); ffma2(a1[3], xb.y, w1d);
            ffma2(a1[4], xc.x, w1d); ffma2(a1[5], xc.y, w1d);
            ffma2(a1[6], xd.x, w1d); ffma2(a1[7], xd.y, w1d);
        }
    }

    // --- gate mix + store (compacted order == output order) ---
    float f0 = filler[c0], f1 = filler[c1];
    float* ob = out + (size_t)(b * 4096 + j0) * 512;
#pragma unroll
    for (int rp = 0; rp < 8; rp++) {
        float ya0, yb0, ya1, yb1;
        unpack2(a0[rp], ya0, yb0);
        unpack2(a1[rp], ya1, yb1);
        int r0 = 2 * rp, r1 = 2 * rp + 1;
        if (v_sh[r0]) {
            float g = g_sh[r0];
            ob[r0 * 512 + c0] = g * ya0 + (1.f - g) * cn[r0 * 512 + c0];
            ob[r0 * 512 + c1] = g * ya1 + (1.f - g) * cn[r0 * 512 + c1];
        } else {
            ob[r0 * 512 + c0] = f0;
            ob[r0 * 512 + c1] = f1;
        }
        if (v_sh[r1]) {
            float g = g_sh[r1];
            ob[r1 * 512 + c0] = g * yb0 + (1.f - g) * cn[r1 * 512 + c0];
            ob[r1 * 512 + c1] = g * yb1 + (1.f - g) * cn[r1 * 512 + c1];
        } else {
            ob[r1 * 512 + c0] = f0;
            ob[r1 * 512 + c1] = f1;
        }
    }
}

// ---------------- launch ----------------
extern "C" void kernel_launch(void* const* d_in, const int* in_sizes, int n_in,
                              void* d_out, int out_size) {
    (void)in_sizes;
    (void)n_in;
    (void)out_size;
    const float* tok = (const float*)d_in[0];
    // d_in[1] = token_ids_mask: unused by the reference
    const float* ch = (const float*)d_in[2];
    const int* cmask = (const int*)d_in[3];  // bool -> int32 in harness
    const float* filler = (const float*)d_in[4];
    const float* w_pre = (const float*)d_in[5];
    const float* w_tok = (const float*)d_in[6];
    const float* w_char = (const float*)d_in[7];
    const float* Wd = (const float*)d_in[8];
    const float* Wp = (const float*)d_in[9];
    const float* Wf = (const float*)d_in[10];
    float* out = (float*)d_out;

    cudaFuncSetAttribute(k_params, cudaFuncAttributeMaxDynamicSharedMemorySize, 115200);
    cudaFuncSetAttribute(k_fusion, cudaFuncAttributeMaxDynamicSharedMemorySize, 107136);

    k_scan<<<16, 256>>>(cmask);
    k_params<<<256, 256, 115200>>>(tok, w_pre, w_tok, Wd, Wp);
    k_fusion<<<4096, 256, 107136>>>(ch, w_char, Wf, filler, out);
}

// round 3
// speedup vs baseline: 6.8382x; 6.8382x over previous
#include <cuda_runtime.h>
#include <cstdint>

#define EPS 1e-6f

// ---------------- device scratch (no allocations allowed) ----------------
__device__ float4 g_params[4096];        // per (b,t): {1+scale, shift, sigmoid(gate), 0}
__device__ int    g_valid[16 * 4096];    // per batch: compacted flat indices (t*16+c)
__device__ int    g_count[16];           // per batch: number of valid chars
__device__ float  g_inv[16 * 4096];      // per compacted row: rmsnorm 1/rms
__device__ float  g_xn[4096 * 1024];     // normalized tokens (tf32-rounded)
__device__ float  g_feats[4096 * 512];   // GEMM1 output
__device__ float  g_u[65536 * 512];      // modulated-silu activations (tf32-rounded)

// ---------------- helpers ----------------
__device__ __forceinline__ float silu_f(float z) { return z / (1.0f + __expf(-z)); }
__device__ __forceinline__ float tf32r(float x) {
    uint32_t o;
    asm("cvt.rna.tf32.f32 %0, %1;" : "=r"(o) : "f"(x));
    return __uint_as_float(o);
}
__device__ __forceinline__ uint32_t smem_u32(const void* p) {
    return (uint32_t)__cvta_generic_to_shared(p);
}
__device__ __forceinline__ void cp16(uint32_t d, const void* s) {
    asm volatile("cp.async.cg.shared.global [%0], [%1], 16;" ::"r"(d), "l"(s));
}
#define CP_COMMIT asm volatile("cp.async.commit_group;")
#define CP_WAIT0 asm volatile("cp.async.wait_group 0;")

__device__ __forceinline__ void mma8(float* c, const uint32_t* a, const uint32_t* b) {
    asm volatile(
        "mma.sync.aligned.m16n8k8.row.col.f32.tf32.tf32.f32 "
        "{%0,%1,%2,%3}, {%4,%5,%6,%7}, {%8,%9}, {%0,%1,%2,%3};"
        : "+f"(c[0]), "+f"(c[1]), "+f"(c[2]), "+f"(c[3])
        : "r"(a[0]), "r"(a[1]), "r"(a[2]), "r"(a[3]), "r"(b[0]), "r"(b[1]));
}

// ---------------- kernel 0: per-batch mask scan / compaction ----------------
// char_ids_mask is bool promoted to int32 by the harness.
__global__ void k_scan(const int* __restrict__ mask) {
    int b = blockIdx.x, tid = threadIdx.x;
    __shared__ int s[256];
    const int* m = mask + b * 4096 + tid * 16;
    unsigned flags = 0;
    int cnt = 0;
#pragma unroll
    for (int i = 0; i < 16; i++)
        if (m[i] != 0) { flags |= (1u << i); cnt++; }
    s[tid] = cnt;
    __syncthreads();
    for (int off = 1; off < 256; off <<= 1) {
        int v = (tid >= off) ? s[tid - off] : 0;
        __syncthreads();
        s[tid] += v;
        __syncthreads();
    }
    int base = s[tid] - cnt;
    int ib = b * 4096;
#pragma unroll
    for (int i = 0; i < 16; i++)
        if (flags & (1u << i)) g_valid[ib + base++] = tid * 16 + i;
    if (tid == 255) g_count[b] = s[255];
}

// ---------------- kernel 1: token rmsnorm -> g_xn (tf32 rounded) ----------------
__global__ __launch_bounds__(256) void k_norm_tok(const float* __restrict__ tok,
                                                  const float* __restrict__ w_pre) {
    int warp = threadIdx.x >> 5, lane = threadIdx.x & 31;
    int row = blockIdx.x * 8 + warp;  // 4096 rows
    const float4* x = (const float4*)(tok + (size_t)row * 1024);
    const float4* w = (const float4*)w_pre;
    float4 v[8];
    float ss = 0.f;
#pragma unroll
    for (int i = 0; i < 8; i++) {
        float4 a = x[lane + 32 * i];
        v[i] = a;
        ss += a.x * a.x + a.y * a.y + a.z * a.z + a.w * a.w;
    }
#pragma unroll
    for (int o = 16; o >= 1; o >>= 1) ss += __shfl_xor_sync(0xffffffffu, ss, o);
    float inv = rsqrtf(ss * (1.0f / 1024.0f) + EPS);
    float4* out = (float4*)(g_xn + (size_t)row * 1024);
#pragma unroll
    for (int i = 0; i < 8; i++) {
        float4 ww = w[lane + 32 * i];
        float4 r;
        r.x = tf32r(v[i].x * inv * ww.x);
        r.y = tf32r(v[i].y * inv * ww.y);
        r.z = tf32r(v[i].z * inv * ww.z);
        r.w = tf32r(v[i].w * inv * ww.w);
        out[lane + 32 * i] = r;
    }
}

// ---------------- shared GEMM core: C(128x128) += A(128xK) @ B(128xK)^T ----------------
// 256 threads = 8 warps as 4(M) x 2(N); warp tile 32x64; mma m16n8k8 tf32.
// smem: double-buffered As[128][36], Bs[128][36] (stride 36 -> conflict-free frags).
template <int NC>
__device__ __forceinline__ void gemm_tiles(const float* __restrict__ A,
                                           const float* __restrict__ B, int lda, int ldb,
                                           int rowBase, int nBase, float (&acc)[2][8][4],
                                           float* sm) {
    float* As[2] = {sm, sm + 2 * 128 * 36};
    float* Bs[2] = {sm + 128 * 36, sm + 3 * 128 * 36};
    int tid = threadIdx.x;
    int srow = tid >> 3, scol4 = (tid & 7) * 4;
    int wid = tid >> 5, lane = tid & 31;
    int warpM = wid >> 1, warpN = wid & 1;
    int g = lane >> 2, qc = lane & 3;

    {  // prefetch chunk 0
        const float* Ag = A + (size_t)(rowBase + srow) * lda + scol4;
        const float* Bg = B + (size_t)(nBase + srow) * ldb + scol4;
#pragma unroll
        for (int it = 0; it < 4; it++) {
            cp16(smem_u32(As[0] + (srow + 32 * it) * 36 + scol4), Ag + (size_t)(32 * it) * lda);
            cp16(smem_u32(Bs[0] + (srow + 32 * it) * 36 + scol4), Bg + (size_t)(32 * it) * ldb);
        }
        CP_COMMIT;
    }
    CP_WAIT0;
    __syncthreads();

    for (int kc = 0; kc < NC; kc++) {
        int cur = kc & 1;
        if (kc + 1 < NC) {
            int nxt = cur ^ 1;
            const float* Ag = A + (size_t)(rowBase + srow) * lda + (kc + 1) * 32 + scol4;
            const float* Bg = B + (size_t)(nBase + srow) * ldb + (kc + 1) * 32 + scol4;
#pragma unroll
            for (int it = 0; it < 4; it++) {
                cp16(smem_u32(As[nxt] + (srow + 32 * it) * 36 + scol4),
                     Ag + (size_t)(32 * it) * lda);
                cp16(smem_u32(Bs[nxt] + (srow + 32 * it) * 36 + scol4),
                     Bg + (size_t)(32 * it) * ldb);
            }
            CP_COMMIT;
        }
        const float* as = As[cur];
        const float* bs = Bs[cur];
#pragma unroll
        for (int ks = 0; ks < 4; ks++) {
            int k0 = ks * 8;
            uint32_t af[2][4];
#pragma unroll
            for (int mi = 0; mi < 2; mi++) {
                int r = warpM * 32 + mi * 16 + g;
                af[mi][0] = __float_as_uint(as[r * 36 + k0 + qc]);
                af[mi][1] = __float_as_uint(as[(r + 8) * 36 + k0 + qc]);
                af[mi][2] = __float_as_uint(as[r * 36 + k0 + qc + 4]);
                af[mi][3] = __float_as_uint(as[(r + 8) * 36 + k0 + qc + 4]);
            }
#pragma unroll
            for (int ni = 0; ni < 8; ni++) {
                int n = warpN * 64 + ni * 8 + g;
                uint32_t bf[2];
                bf[0] = __float_as_uint(bs[n * 36 + k0 + qc]);
                bf[1] = __float_as_uint(bs[n * 36 + k0 + qc + 4]);
                mma8(acc[0][ni], af[0], bf);
                mma8(acc[1][ni], af[1], bf);
            }
        }
        if (kc + 1 < NC) { CP_WAIT0; }
        __syncthreads();
    }
}

// ---------------- kernel 2: GEMM1 feats = xn @ Wd^T ----------------
__global__ __launch_bounds__(256) void k_gemm1(const float* __restrict__ Wd) {
    extern __shared__ float sm[];
    float acc[2][8][4] = {};
    int rowTile = blockIdx.x >> 2, nTile = blockIdx.x & 3;
    gemm_tiles<32>(g_xn, Wd, 1024, 1024, rowTile * 128, nTile * 128, acc, sm);
    int tid = threadIdx.x, wid = tid >> 5, lane = tid & 31;
    int warpM = wid >> 1, warpN = wid & 1, g = lane >> 2, qc = lane & 3;
#pragma unroll
    for (int mi = 0; mi < 2; mi++)
#pragma unroll
        for (int ni = 0; ni < 8; ni++) {
            int r = rowTile * 128 + warpM * 32 + mi * 16 + g;
            int c = nTile * 128 + warpN * 64 + ni * 8 + qc * 2;
            float2 v0 = {acc[mi][ni][0], acc[mi][ni][1]};
            float2 v1 = {acc[mi][ni][2], acc[mi][ni][3]};
            *(float2*)(g_feats + (size_t)r * 512 + c) = v0;
            *(float2*)(g_feats + (size_t)(r + 8) * 512 + c) = v1;
        }
}

// ---------------- kernel 3: feats rmsnorm + silu + W_proj -> params ----------------
__global__ __launch_bounds__(256) void k_post(const float* __restrict__ w_tok,
                                              const float* __restrict__ Wp) {
    int warp = threadIdx.x >> 5, lane = threadIdx.x & 31;
    int row = blockIdx.x * 8 + warp;  // 4096 rows
    const float4* f = (const float4*)(g_feats + (size_t)row * 512);
    float4 v[4];
    float ss = 0.f;
#pragma unroll
    for (int i = 0; i < 4; i++) {
        float4 a = f[lane + 32 * i];
        v[i] = a;
        ss += a.x * a.x + a.y * a.y + a.z * a.z + a.w * a.w;
    }
#pragma unroll
    for (int o = 16; o >= 1; o >>= 1) ss += __shfl_xor_sync(0xffffffffu, ss, o);
    float inv = rsqrtf(ss * (1.0f / 512.0f) + EPS);
    const float4* wt = (const float4*)w_tok;
    const float4* wp0 = (const float4*)Wp;
    const float4* wp1 = (const float4*)(Wp + 512);
    const float4* wp2 = (const float4*)(Wp + 1024);
    float p0 = 0.f, p1 = 0.f, p2 = 0.f;
#pragma unroll
    for (int i = 0; i < 4; i++) {
        float4 ww = wt[lane + 32 * i];
        float4 a = v[i];
        float s0 = silu_f(a.x * inv * ww.x), s1 = silu_f(a.y * inv * ww.y);
        float s2 = silu_f(a.z * inv * ww.z), s3 = silu_f(a.w * inv * ww.w);
        float4 q0 = wp0[lane + 32 * i], q1 = wp1[lane + 32 * i], q2 = wp2[lane + 32 * i];
        p0 += s0 * q0.x + s1 * q0.y + s2 * q0.z + s3 * q0.w;
        p1 += s0 * q1.x + s1 * q1.y + s2 * q1.z + s3 * q1.w;
        p2 += s0 * q2.x + s1 * q2.y + s2 * q2.z + s3 * q2.w;
    }
#pragma unroll
    for (int o = 16; o >= 1; o >>= 1) {
        p0 += __shfl_xor_sync(0xffffffffu, p0, o);
        p1 += __shfl_xor_sync(0xffffffffu, p1, o);
        p2 += __shfl_xor_sync(0xffffffffu, p2, o);
    }
    if (lane == 0) {
        float4 pr;
        pr.x = 1.0f + p0;
        pr.y = p1;
        pr.z = 1.0f / (1.0f + __expf(-p2));
        pr.w = 0.f;
        g_params[row] = pr;
    }
}

// ---------------- kernel 4: char rmsnorm + modulated silu -> g_u, g_inv ----------------
__global__ __launch_bounds__(256) void k_norm_char(const float* __restrict__ ch,
                                                   const float* __restrict__ w_char) {
    int warp = threadIdx.x >> 5, lane = threadIdx.x & 31;
    int jj = blockIdx.x * 8 + warp;  // compacted slot (b*4096 + j)
    int b = jj >> 12, j = jj & 4095;
    if (j >= g_count[b]) return;
    int flat = g_valid[b * 4096 + j];
    float4 p = g_params[b * 256 + (flat >> 4)];
    const float4* x = (const float4*)(ch + (size_t)(b * 4096 + flat) * 512);
    float4 v[4];
    float ss = 0.f;
#pragma unroll
    for (int i = 0; i < 4; i++) {
        float4 a = x[lane + 32 * i];
        v[i] = a;
        ss += a.x * a.x + a.y * a.y + a.z * a.z + a.w * a.w;
    }
#pragma unroll
    for (int o = 16; o >= 1; o >>= 1) ss += __shfl_xor_sync(0xffffffffu, ss, o);
    float inv = rsqrtf(ss * (1.0f / 512.0f) + EPS);
    if (lane == 0) g_inv[b * 4096 + j] = inv;
    const float4* w = (const float4*)w_char;
    float4* out = (float4*)(g_u + (size_t)(b * 4096 + j) * 512);
#pragma unroll
    for (int i = 0; i < 4; i++) {
        float4 ww = w[lane + 32 * i];
        float4 a = v[i];
        float4 r;
        r.x = tf32r(silu_f(a.x * inv * ww.x * p.x + p.y));
        r.y = tf32r(silu_f(a.y * inv * ww.y * p.x + p.y));
        r.z = tf32r(silu_f(a.z * inv * ww.z * p.x + p.y));
        r.w = tf32r(silu_f(a.w * inv * ww.w * p.x + p.y));
        out[lane + 32 * i] = r;
    }
}

// ---------------- kernel 5: GEMM2 + gated mix + filler epilogue ----------------
__global__ __launch_bounds__(256) void k_gemm_fuse(const float* __restrict__ ch,
                                                   const float* __restrict__ w_char,
                                                   const float* __restrict__ Wf,
                                                   const float* __restrict__ filler,
                                                   float* __restrict__ out) {
    int rowTile = blockIdx.x >> 2, nTile = blockIdx.x & 3;
    int b = rowTile >> 5, j0 = (rowTile & 31) * 128;
    int cnt = g_count[b];
    int tid = threadIdx.x;

    if (j0 >= cnt) {  // entire tile filler: broadcast
        int f4c = tid & 31, r0 = tid >> 5;
        float4 fv = ((const float4*)filler)[nTile * 32 + f4c];
        float4* ob = (float4*)(out + (size_t)(b * 4096 + j0) * 512 + nTile * 128);
#pragma unroll
        for (int it = 0; it < 16; it++) ob[(size_t)(r0 + 8 * it) * 128 + f4c] = fv;
        return;
    }

    extern __shared__ float sm[];
    float acc[2][8][4] = {};
    gemm_tiles<16>(g_u, Wf, 512, 512, b * 4096 + j0, nTile * 128, acc, sm);

    int wid = tid >> 5, lane = tid & 31;
    int warpM = wid >> 1, warpN = wid & 1, g = lane >> 2, qc = lane & 3;
    const float2* fil2 = (const float2*)filler;
    const float2* wch2 = (const float2*)w_char;
#pragma unroll
    for (int mi = 0; mi < 2; mi++)
#pragma unroll
        for (int rr = 0; rr < 2; rr++) {
            int lr = warpM * 32 + mi * 16 + g + rr * 8;
            int j = j0 + lr;
            bool val = j < cnt;
            int flat = val ? g_valid[b * 4096 + j] : 0;
            float inv = val ? g_inv[b * 4096 + j] : 0.f;
            float gate = val ? g_params[b * 256 + (flat >> 4)].z : 0.f;
            const float2* chrow = (const float2*)(ch + (size_t)(b * 4096 + flat) * 512);
            float* orow = out + (size_t)(b * 4096 + j) * 512;
#pragma unroll
            for (int ni = 0; ni < 8; ni++) {
                int c = nTile * 128 + warpN * 64 + ni * 8 + qc * 2;
                float a0 = acc[mi][ni][rr * 2 + 0], a1 = acc[mi][ni][rr * 2 + 1];
                float2 o;
                if (val) {
                    float2 cv = chrow[c >> 1];
                    float2 ww = wch2[c >> 1];
                    o.x = gate * a0 + (1.f - gate) * (cv.x * inv * ww.x);
                    o.y = gate * a1 + (1.f - gate) * (cv.y * inv * ww.y);
                } else {
                    o = fil2[c >> 1];
                }
                *(float2*)(orow + c) = o;
            }
        }
}

// ---------------- launch ----------------
extern "C" void kernel_launch(void* const* d_in, const int* in_sizes, int n_in,
                              void* d_out, int out_size) {
    (void)in_sizes;
    (void)n_in;
    (void)out_size;
    const float* tok = (const float*)d_in[0];
    // d_in[1] = token_ids_mask: unused by the reference
    const float* ch = (const float*)d_in[2];
    const int* cmask = (const int*)d_in[3];  // bool -> int32
    const float* filler = (const float*)d_in[4];
    const float* w_pre = (const float*)d_in[5];
    const float* w_tok = (const float*)d_in[6];
    const float* w_char = (const float*)d_in[7];
    const float* Wd = (const float*)d_in[8];
    const float* Wp = (const float*)d_in[9];
    const float* Wf = (const float*)d_in[10];
    float* out = (float*)d_out;

    cudaFuncSetAttribute(k_gemm1, cudaFuncAttributeMaxDynamicSharedMemorySize, 73728);
    cudaFuncSetAttribute(k_gemm_fuse, cudaFuncAttributeMaxDynamicSharedMemorySize, 73728);

    k_scan<<<16, 256>>>(cmask);
    k_norm_tok<<<512, 256>>>(tok, w_pre);
    k_gemm1<<<128, 256, 73728>>>(Wd);
    k_post<<<512, 256>>>(w_tok, Wp);
    k_norm_char<<<8192, 256>>>(ch, w_char);
    k_gemm_fuse<<<2048, 256, 73728>>>(ch, w_char, Wf, filler, out);
}